// round 17
// baseline (speedup 1.0000x reference)
#include <cuda_runtime.h>
#include <cuda_bf16.h>
#include <cstdint>

#define HWN    4096
#define CDIM   256
#define KCODES 1024
#define BATCH  16
#define NPIX   (BATCH * HWN)
#define MARGIN 0.012f

// ---------------------------------------------------------------------------
// Device-global scratch
// ---------------------------------------------------------------------------
__device__ __align__(16) __nv_bfloat16 g_cbh[KCODES * CDIM];
__device__ __align__(16) __nv_bfloat16 g_cbl[KCODES * CDIM];
__device__ float g_ct[CDIM * KCODES];   // codebook transposed (exact fixup)
__device__ float g_c2[KCODES];
__device__ int   g_inds[NPIX];
__device__ int   g_flag[NPIX];
__device__ int   g_nflag;
__device__ float g_loss;

// ---------------------------------------------------------------------------
__device__ __forceinline__ void split2(float v, uint16_t& h, uint16_t& l) {
    __nv_bfloat16 bh = __float2bfloat16_rn(v);
    __nv_bfloat16 bl = __float2bfloat16_rn(v - __bfloat162float(bh));
    h = __bfloat16_as_ushort(bh);
    l = __bfloat16_as_ushort(bl);
}

__device__ __forceinline__ uint32_t smem_u32(const void* p) {
    uint32_t a;
    asm("{ .reg .u64 t; cvta.to.shared.u64 t, %1; cvt.u32.u64 %0, t; }" : "=r"(a) : "l"(p));
    return a;
}
__device__ __forceinline__ void cp16(uint32_t dst, const void* src) {
    asm volatile("cp.async.cg.shared.global [%0], [%1], 16;" :: "r"(dst), "l"(src) : "memory");
}
#define CP_COMMIT() asm volatile("cp.async.commit_group;" ::: "memory")
#define CP_WAIT1()  asm volatile("cp.async.wait_group 1;" ::: "memory")
#define CP_WAIT0()  asm volatile("cp.async.wait_group 0;" ::: "memory")

__device__ __forceinline__ void ldsm4(uint32_t* r, uint32_t addr) {
    asm volatile("ldmatrix.sync.aligned.m8n8.x4.shared.b16 {%0,%1,%2,%3}, [%4];"
                 : "=r"(r[0]), "=r"(r[1]), "=r"(r[2]), "=r"(r[3]) : "r"(addr));
}
__device__ __forceinline__ void mma16816(float* d, const uint32_t* a,
                                         const uint32_t* b) {
    asm volatile(
        "mma.sync.aligned.m16n8k16.row.col.f32.bf16.bf16.f32 "
        "{%0,%1,%2,%3}, {%4,%5,%6,%7}, {%8,%9}, {%0,%1,%2,%3};"
        : "+f"(d[0]), "+f"(d[1]), "+f"(d[2]), "+f"(d[3])
        : "r"(a[0]), "r"(a[1]), "r"(a[2]), "r"(a[3]), "r"(b[0]), "r"(b[1]));
}

// ---------------------------------------------------------------------------
// Prep kernels
// ---------------------------------------------------------------------------
__global__ void prep_transpose(const float* __restrict__ cb) {
    __shared__ float tile[32][33];
    int k0 = blockIdx.x * 32, c0 = blockIdx.y * 32;
    int tx = threadIdx.x & 31, r0 = threadIdx.x >> 5;
#pragma unroll
    for (int i = 0; i < 4; i++)
        tile[r0 + i * 8][tx] = cb[(size_t)(k0 + r0 + i * 8) * CDIM + c0 + tx];
    __syncthreads();
#pragma unroll
    for (int i = 0; i < 4; i++)
        g_ct[(size_t)(c0 + r0 + i * 8) * KCODES + k0 + tx] = tile[tx][r0 + i * 8];
    if (blockIdx.x == 0 && blockIdx.y == 0 && threadIdx.x == 0) {
        g_loss = 0.0f;
        g_nflag = 0;
    }
}

__global__ void prep_c2(const float* __restrict__ cb) {
    int k = blockIdx.x, lane = threadIdx.x;
    float s = 0.0f;
#pragma unroll
    for (int c = lane; c < CDIM; c += 32) {
        float v = cb[(size_t)k * CDIM + c];
        s += v * v;
    }
#pragma unroll
    for (int o = 16; o; o >>= 1) s += __shfl_xor_sync(0xffffffffu, s, o);
    if (lane == 0) g_c2[k] = s;
}

__global__ __launch_bounds__(256) void split_cb(const float* __restrict__ cb) {
    int i = blockIdx.x * 256 + threadIdx.x;
    float v = cb[i];
    uint16_t h, l;
    split2(v, h, l);
    g_cbh[i] = __ushort_as_bfloat16(h);
    g_cbl[i] = __ushort_as_bfloat16(l);
}

// ---------------------------------------------------------------------------
// Tensor-core approximate GEMM + top-2 argmin + flagging.
// CTA: 64 pixels x 1024 codes, 16 warps (4/SMSP), warp tile 32px x 16 codes.
// A split fused in-prologue from fp32 x. B chunks (128 codes x 64 ch x 2
// splits) 3-stage cp.async pipeline, single sync per chunk.
// ---------------------------------------------------------------------------
#define APITCH 528
#define BPITCH 144
#define OFF_AH 0
#define OFF_AL 33792
#define OFF_B  67584
#define BUFSZ  36864
#define SPLSZ  18432
#define OFF_C2 178176
#define OFF_RB 182272
#define OFF_RS 184320
#define OFF_RI 186368
#define SMEM_GEMM 188416

__global__ __launch_bounds__(512, 1) void gemm_mma(const float* __restrict__ x) {
    extern __shared__ __align__(16) unsigned char smem[];
    const uint32_t smb = smem_u32(smem);
    const int tid = threadIdx.x;
    const int wid = tid >> 5, lane = tid & 31;
    const int g = lane >> 2, tig = lane & 3;
    const int warpM = wid & 1;                // 32 px per M-half
    const int warpN = wid >> 1;               // 8 N-groups, 16 codes each
    const int laneR = lane & 15, laneK = (lane >> 4) << 3;

    auto issueB = [&](int ch, int buf) {
        const int nt = ch >> 2, kc = ch & 3;
        const uint32_t dbase = smb + OFF_B + buf * BUFSZ;
#pragma unroll
        for (int s = 0; s < 2; s++) {
            const uint4* src = (const uint4*)(s ? g_cbl : g_cbh);
            uint32_t db = dbase + s * SPLSZ;
#pragma unroll
            for (int i = 0; i < 2; i++) {
                int idx = tid + i * 512;
                int r = idx >> 3, q = idx & 7;
                cp16(db + r * BPITCH + q * 16, src + (nt * 128 + r) * 32 + kc * 8 + q);
            }
        }
        CP_COMMIT();
    };

    // ---- pipeline prologue: chunks 0,1 in flight ----
    issueB(0, 0);
    issueB(1, 1);

    // ---- fused A load + split (overlaps with cp.async) ----
    {
        const int b = blockIdx.x >> 6;
        const int n0 = (blockIdx.x & 63) * 64;
        const int px = tid & 63, cg8 = tid >> 6;   // 8 channel groups of 32
        const float* xb = x + (size_t)b * CDIM * HWN + n0 + px;
        unsigned char* ahb = smem + OFF_AH + px * APITCH;
        unsigned char* alb = smem + OFF_AL + px * APITCH;
#pragma unroll 8
        for (int i = 0; i < 32; i++) {
            int c = cg8 * 32 + i;
            float v = __ldg(xb + (size_t)c * HWN);
            uint16_t h, l;
            split2(v, h, l);
            *(uint16_t*)(ahb + c * 2) = h;
            *(uint16_t*)(alb + c * 2) = l;
        }
#pragma unroll
        for (int i = 0; i < 2; i++)
            ((float*)(smem + OFF_C2))[tid + i * 512] = g_c2[tid + i * 512];
    }

    float bestv[4], secv[4];
    int bidx[4];
#pragma unroll
    for (int r = 0; r < 4; r++) { bestv[r] = 3.4e38f; secv[r] = 3.4e38f; bidx[r] = 0; }
    const float* c2s = (const float*)(smem + OFF_C2);

    float acc[2][2][4];
    const uint32_t aAddrH = smb + OFF_AH + (warpM * 32 + laneR) * APITCH + laneK * 2;
    const uint32_t aAddrL = smb + OFF_AL + (warpM * 32 + laneR) * APITCH + laneK * 2;
    const uint32_t bAddr  = smb + OFF_B + (warpN * 16 + laneR) * BPITCH + laneK * 2;

#pragma unroll 1
    for (int ci = 0; ci < 32; ci++) {
        const int nt = ci >> 2, kc = ci & 3, buf = ci % 3;
        if (ci == 31) { CP_WAIT0(); } else { CP_WAIT1(); }
        __syncthreads();   // publishes chunk ci; guards buf (ci+2)%3 reuse

        if (kc == 0) {
#pragma unroll
            for (int mi = 0; mi < 2; mi++)
#pragma unroll
                for (int ni = 0; ni < 2; ni++)
#pragma unroll
                    for (int e = 0; e < 4; e++) acc[mi][ni][e] = 0.0f;
        }

        const uint32_t bH = bAddr + buf * BUFSZ;
        const uint32_t bL = bH + SPLSZ;
#pragma unroll
        for (int ks = 0; ks < 4; ks++) {
            const uint32_t ak = (uint32_t)(kc * 64 + ks * 16) * 2;
            uint32_t ah[2][4], al[2][4];
#pragma unroll
            for (int mi = 0; mi < 2; mi++) {
                ldsm4(ah[mi], aAddrH + mi * (16 * APITCH) + ak);
                ldsm4(al[mi], aAddrL + mi * (16 * APITCH) + ak);
            }
            uint32_t bh[2][2], bl[2][2], r4[4];
            ldsm4(r4, bH + ks * 32);
            bh[0][0] = r4[0]; bh[1][0] = r4[1]; bh[0][1] = r4[2]; bh[1][1] = r4[3];
            ldsm4(r4, bL + ks * 32);
            bl[0][0] = r4[0]; bl[1][0] = r4[1]; bl[0][1] = r4[2]; bl[1][1] = r4[3];

#pragma unroll
            for (int mi = 0; mi < 2; mi++)
#pragma unroll
                for (int ni = 0; ni < 2; ni++)
                    mma16816(acc[mi][ni], ah[mi], bh[ni]);
#pragma unroll
            for (int mi = 0; mi < 2; mi++)
#pragma unroll
                for (int ni = 0; ni < 2; ni++)
                    mma16816(acc[mi][ni], ah[mi], bl[ni]);
#pragma unroll
            for (int mi = 0; mi < 2; mi++)
#pragma unroll
                for (int ni = 0; ni < 2; ni++)
                    mma16816(acc[mi][ni], al[mi], bh[ni]);
        }

        if (kc == 3) {
            // fold into per-lane top-2 (ascending code order per row slot)
#pragma unroll
            for (int ni = 0; ni < 2; ni++) {
                int cg = nt * 128 + warpN * 16 + ni * 8 + tig * 2;
                float c20 = c2s[cg], c21 = c2s[cg + 1];
#pragma unroll
                for (int mi = 0; mi < 2; mi++) {
#pragma unroll
                    for (int e = 0; e < 4; e++) {
                        int r4s = mi * 2 + (e >> 1);
                        float v = fmaf(-2.0f, acc[mi][ni][e], (e & 1) ? c21 : c20);
                        int k = cg + (e & 1);
                        if (v < bestv[r4s]) {
                            secv[r4s] = bestv[r4s];
                            bestv[r4s] = v;
                            bidx[r4s] = k;
                        } else if (v < secv[r4s]) {
                            secv[r4s] = v;
                        }
                    }
                }
            }
        }

        if (ci < 30) issueB(ci + 2, (ci + 2) % 3);
    }

    // ---- quad merge (lanes with same g share rows) ----
#pragma unroll
    for (int o = 1; o <= 2; o <<= 1) {
#pragma unroll
        for (int r = 0; r < 4; r++) {
            float ob = __shfl_xor_sync(0xffffffffu, bestv[r], o);
            float os = __shfl_xor_sync(0xffffffffu, secv[r], o);
            int oi = __shfl_xor_sync(0xffffffffu, bidx[r], o);
            bool take = (ob < bestv[r]) || (ob == bestv[r] && oi < bidx[r]);
            float loser = take ? bestv[r] : ob;
            if (take) { bestv[r] = ob; bidx[r] = oi; }
            secv[r] = fminf(fminf(secv[r], os), loser);
        }
    }

    float* redb = (float*)(smem + OFF_RB);
    float* reds = (float*)(smem + OFF_RS);
    int*   redi = (int*)(smem + OFF_RI);
    if (tig == 0) {
#pragma unroll
        for (int r4s = 0; r4s < 4; r4s++) {
            int row = warpM * 32 + (r4s >> 1) * 16 + (r4s & 1) * 8 + g;  // 0..63
            redb[warpN * 64 + row] = bestv[r4s];
            reds[warpN * 64 + row] = secv[r4s];
            redi[warpN * 64 + row] = bidx[r4s];
        }
    }
    __syncthreads();

    if (tid < 64) {
        float bv = 3.4e38f, sv = 3.4e38f;
        int bi = 0x7fffffff;
#pragma unroll
        for (int w = 0; w < 8; w++) {
            float ob = redb[w * 64 + tid];
            float os = reds[w * 64 + tid];
            int oi = redi[w * 64 + tid];
            bool take = (ob < bv) || (ob == bv && oi < bi);
            float loser = take ? bv : ob;
            if (take) { bv = ob; bi = oi; }
            sv = fminf(fminf(sv, os), loser);
        }
        int pixel = blockIdx.x * 64 + tid;
        g_inds[pixel] = bi;
        if (sv - bv < MARGIN) {
            int slot = atomicAdd(&g_nflag, 1);
            g_flag[slot] = pixel;
        }
    }
}

// ---------------------------------------------------------------------------
// Exact fp32 fixup: 16 flagged pixels per block x all 1024 codes.
// ---------------------------------------------------------------------------
__global__ __launch_bounds__(256) void fixup(const float* __restrict__ x) {
    int nflag = g_nflag;
    int base = blockIdx.x * 16;
    if (base >= nflag) return;

    __shared__ float As[32][17];
    __shared__ float Bs[32][64];
    __shared__ float rv[16][17];
    __shared__ int   ri[16][17];
    __shared__ int   pid[16];
    __shared__ size_t pbase[16];

    const int tid = threadIdx.x;
    if (tid < 16) {
        int src = base + tid;
        if (src >= nflag) src = base;
        int p = g_flag[src];
        pid[tid] = p;
        pbase[tid] = (size_t)(p >> 12) * CDIM * HWN + (p & 4095);
    }
    __syncthreads();

    const int tx = tid & 15, ty = tid >> 4;
    float best = 3.4e38f;
    int besti = 0;

    for (int kt = 0; kt < 16; kt++) {
        float acc[4] = {0.0f, 0.0f, 0.0f, 0.0f};
#pragma unroll 1
        for (int cc = 0; cc < CDIM; cc += 32) {
#pragma unroll
            for (int i = 0; i < 2; i++) {
                int idx = tid + i * 256;
                int r = idx >> 4, px = idx & 15;
                As[r][px] = x[pbase[px] + (size_t)(cc + r) * HWN];
            }
#pragma unroll
            for (int i = 0; i < 8; i++) {
                int idx = tid + i * 256;
                int r = idx >> 6, col = idx & 63;
                Bs[r][col] = g_ct[(size_t)(cc + r) * KCODES + kt * 64 + col];
            }
            __syncthreads();
#pragma unroll
            for (int c = 0; c < 32; c++) {
                float a = As[c][ty];
                float4 b4 = *(const float4*)&Bs[c][tx * 4];
                acc[0] = fmaf(a, b4.x, acc[0]);
                acc[1] = fmaf(a, b4.y, acc[1]);
                acc[2] = fmaf(a, b4.z, acc[2]);
                acc[3] = fmaf(a, b4.w, acc[3]);
            }
            __syncthreads();
        }
#pragma unroll
        for (int j = 0; j < 4; j++) {
            int k = kt * 64 + tx * 4 + j;
            float d = fmaf(-2.0f, acc[j], g_c2[k]);
            if (d < best) { best = d; besti = k; }
        }
    }

    rv[ty][tx] = best;
    ri[ty][tx] = besti;
    __syncthreads();
    if (tid < 16) {
        float bv = 3.4e38f;
        int bi = 0x7fffffff;
#pragma unroll
        for (int t = 0; t < 16; t++) {
            float v = rv[tid][t];
            int id = ri[tid][t];
            if (v < bv || (v == bv && id < bi)) { bv = v; bi = id; }
        }
        g_inds[pid[tid]] = bi;   // duplicate pixels write identical values
    }
}

// ---------------------------------------------------------------------------
// Gather + loss
// ---------------------------------------------------------------------------
__global__ __launch_bounds__(256) void gather_loss(const float* __restrict__ x,
                                                   const float* __restrict__ cb,
                                                   float* __restrict__ out) {
    int t = blockIdx.x;
    int b  = t >> 6;
    int n0 = (t & 63) * 64;
    int nl = threadIdx.x & 63;
    int c0 = (threadIdx.x >> 6) * 64;

    int idx = g_inds[b * HWN + n0 + nl];
    const float4* crow = (const float4*)(cb + (size_t)idx * CDIM + c0);
    const float* xb = x   + ((size_t)b * CDIM + c0) * HWN + n0 + nl;
    float*       ob = out + ((size_t)b * CDIM + c0) * HWN + n0 + nl;

    float lsum = 0.0f;
#pragma unroll 4
    for (int i = 0; i < 16; i++) {
        float4 q = __ldg(crow + i);
        float qv[4] = {q.x, q.y, q.z, q.w};
#pragma unroll
        for (int u = 0; u < 4; u++) {
            size_t off = (size_t)(i * 4 + u) * HWN;
            float xv = xb[off];
            ob[off] = qv[u];
            float d = qv[u] - xv;
            lsum = fmaf(d, d, lsum);
        }
    }
#pragma unroll
    for (int o = 16; o; o >>= 1) lsum += __shfl_xor_sync(0xffffffffu, lsum, o);
    __shared__ float ws[8];
    if ((threadIdx.x & 31) == 0) ws[threadIdx.x >> 5] = lsum;
    __syncthreads();
    if (threadIdx.x == 0) {
        float s = 0.0f;
#pragma unroll
        for (int w = 0; w < 8; w++) s += ws[w];
        atomicAdd(&g_loss, s);
    }
}

__global__ void finalize_loss(float* __restrict__ out, int loss_off) {
    out[loss_off] = g_loss * (1.0f / (float)((size_t)BATCH * HWN * CDIM));
}

// ---------------------------------------------------------------------------
extern "C" void kernel_launch(void* const* d_in, const int* in_sizes, int n_in,
                              void* d_out, int out_size) {
    const float* x  = (const float*)d_in[0];   // [16, 256, 64, 64]
    const float* cb = (const float*)d_in[1];   // [1024, 256]
    float* out = (float*)d_out;

    cudaFuncSetAttribute(gemm_mma, cudaFuncAttributeMaxDynamicSharedMemorySize,
                         SMEM_GEMM);

    prep_transpose<<<dim3(KCODES / 32, CDIM / 32), 256>>>(cb);
    prep_c2<<<KCODES, 32>>>(cb);
    split_cb<<<KCODES * CDIM / 256, 256>>>(cb);
    gemm_mma<<<NPIX / 64, 512, SMEM_GEMM>>>(x);
    fixup<<<NPIX / 16, 256>>>(x);
    gather_loss<<<BATCH * HWN / 64, 256>>>(x, cb, out);
    finalize_loss<<<1, 1>>>(out, out_size - 1);
}